// round 3
// baseline (speedup 1.0000x reference)
#include <cuda_runtime.h>

// Problem constants
#define Nn 4096
#define Dd 128
#define H1h 256

typedef unsigned long long u64;

// ---------------- device scratch (no allocations allowed) ----------------
__device__ float g_W [Dd*Dd];     // weight * A
__device__ float g_Wt[Dd*Dd];     // transpose of W (for d-packed GEMM)
__device__ float g_M [Dd*Dd];     // M = I + W^2/D  (fp32, like reference)
__device__ float g_Za[Dd*Dd];     // z ping-pong
__device__ float g_Zb[Dd*Dd];
__device__ float g_Ra[Dd*Dd];     // result ping-pong
__device__ float g_Rb[Dd*Dd];
__device__ float g_s2[H1h];       // row sums of W2
__device__ float g_B2;            // sum of b2
__device__ float g_y [Nn*Dd];     // y = x@W + bias

// device-side table of matrix buffers (addresses resolvable at module load)
__device__ float* const g_tab[5] = { g_M, g_Za, g_Zb, g_Ra, g_Rb };
#define IDX_M  0
#define IDX_ZA 1
#define IDX_ZB 2
#define IDX_RA 3
#define IDX_RB 4

// ---------------- packed f32x2 helpers (2x FP32 throughput on sm_103a) ---
__device__ __forceinline__ u64 pk2(float lo, float hi){
    u64 r; asm("mov.b64 %0, {%1, %2};" : "=l"(r) : "f"(lo), "f"(hi)); return r;
}
__device__ __forceinline__ void upk2(u64 v, float& lo, float& hi){
    asm("mov.b64 {%0, %1}, %2;" : "=f"(lo), "=f"(hi) : "l"(v));
}
__device__ __forceinline__ u64 fma2(u64 a, u64 b, u64 c){
    u64 d; asm("fma.rn.f32x2 %0, %1, %2, %3;" : "=l"(d) : "l"(a), "l"(b), "l"(c));
    return d;
}

// ---------------- prep: W, Wt, M, s2, B2, reg ------------------------------
__global__ void prep_kernel(const float* __restrict__ weight,
                            const float* __restrict__ A,
                            const float* __restrict__ W2,
                            const float* __restrict__ b2,
                            float* __restrict__ d_out)
{
    int t = threadIdx.x; // 256 threads
    float labs = 0.f;
    for (int idx = t; idx < Dd*Dd; idx += 256){
        float w = weight[idx] * A[idx];
        g_W[idx] = w;
        int r = idx >> 7, c = idx & 127;
        g_Wt[c*Dd + r] = w;
        // M = I + square(W)/D exactly as the reference rounds it (fp32)
        float m = (r == c ? 1.f : 0.f) + (w*w)*(1.f/128.f);
        g_M[idx] = m;
        labs += fabsf(w);
    }
    // s2[j] = sum_k W2[j,k]   (W2 is [256,128] row-major)
    {
        float s = 0.f;
        const float* row = W2 + t*128;
        #pragma unroll 4
        for (int k = 0; k < 128; k++) s += row[k];
        g_s2[t] = s;
    }
    if (t == 0){
        float s = 0.f;
        for (int k = 0; k < 128; k++) s += b2[k];
        g_B2 = s;
    }
    // reg = sum |W|
    __shared__ float red[256];
    red[t] = labs;
    __syncthreads();
    for (int s = 128; s > 0; s >>= 1){
        if (t < s) red[t] += red[t + s];
        __syncthreads();
    }
    if (t == 0) d_out[Nn*Dd + 1] = red[0];
}

// ------- reference-mimicking matmul: Dst = L @ R, single-chain k ----------
// One thread per output element; k ascending 0..127, ONE fp32 accumulator,
// pure FMA chain — replicates Eigen-gebp / cuBLAS per-thread accumulation
// so sub-ulp cross terms round away exactly like the reference's backend.
__global__ void mm_kernel(int li, int ri, int di)
{
    const float* __restrict__ L = g_tab[li];
    const float* __restrict__ R = g_tab[ri];
    float*       __restrict__ D = g_tab[di];
    __shared__ __align__(16) float row[128];
    int r = blockIdx.x, j = threadIdx.x;
    row[j] = L[r*128 + j];
    __syncthreads();
    float acc = 0.f;
    #pragma unroll
    for (int k = 0; k < 128; k++)
        acc = fmaf(row[k], R[k*128 + j], acc);
    D[r*128 + j] = acc;
}

// ------- h_val = sum_{i,j} E[j,i]*M[i,j]  - 128, 32-lane strided reduce ----
// Mimics a vectorized (32 partial lanes, contiguous-ascending) fp32 reducer
// followed by a halves-tree horizontal combine.
__global__ void hsum_kernel(int ei, float* __restrict__ d_out)
{
    const float* __restrict__ E = g_tab[ei];
    __shared__ float p[32];
    int l = threadIdx.x;   // 32 threads
    float s = 0.f;
    for (int t = 0; t < 512; t++){
        int idx = l + (t << 5);          // ascending, lane-strided
        int i = idx >> 7, j = idx & 127;
        s += E[j*128 + i] * g_M[i*128 + j];
    }
    p[l] = s;
    __syncthreads();
    for (int st = 16; st > 0; st >>= 1){
        if (l < st) p[l] += p[l + st];
        __syncthreads();
    }
    if (l == 0) d_out[Nn*Dd] = p[0] - 128.f;
}

// ---------------- y = x @ W + bias  (packed over the d reduction) --------
__global__ void gemm_kernel(const float* __restrict__ x,
                            const float* __restrict__ bias)
{
    __shared__ __align__(16) float xs[32][128];
    int t  = threadIdx.x;            // 256
    int n0 = blockIdx.x * 32;        // 128 blocks
    for (int idx = t; idx < 32*128; idx += 256)
        xs[idx >> 7][idx & 127] = x[n0*128 + idx];
    __syncthreads();

    int i  = t & 127;
    int ng = t >> 7;                 // 0..1 -> 16 rows each
    const u64* wrow = (const u64*)(g_Wt + i*128);   // W[:,i] contiguous
    u64 acc[16];
    #pragma unroll
    for (int u = 0; u < 16; u++) acc[u] = 0ULL;

    for (int d2 = 0; d2 < 64; d2 += 2){          // 4 d-values per iter
        u64 w01 = wrow[d2];
        u64 w23 = wrow[d2 + 1];
        #pragma unroll
        for (int u = 0; u < 16; u++){
            const u64* xp = (const u64*)&xs[ng*16 + u][d2*2];
            acc[u] = fma2(xp[0], w01, acc[u]);
            acc[u] = fma2(xp[1], w23, acc[u]);
        }
    }
    float bi = bias[i];
    #pragma unroll
    for (int u = 0; u < 16; u++){
        float p, q; upk2(acc[u], p, q);
        g_y[(n0 + ng*16 + u)*Dd + i] = (p + q) + bi;
    }
}

// ---------------- f[n,i] = sum_j relu(y*W1[i,j]+b1[j])*s2[j] + B2 ---------
__global__ void f_kernel(const float* __restrict__ W1,
                         const float* __restrict__ b1,
                         float* __restrict__ d_out)
{
    __shared__ __align__(16) float a_s[256];
    __shared__ __align__(16) float b_s[256];
    __shared__ __align__(16) float s_s[256];
    int t = threadIdx.x;             // 256
    int i = blockIdx.x;              // 0..127
    a_s[t] = W1[i*H1h + t];
    b_s[t] = b1[t];
    s_s[t] = g_s2[t];
    __syncthreads();

    u64 vv[16], acc[16];
    #pragma unroll
    for (int u = 0; u < 16; u++){
        float v = g_y[(u*256 + t)*Dd + i];
        vv[u]  = pk2(v, v);
        acc[u] = 0ULL;
    }

    #pragma unroll 2
    for (int jp = 0; jp < 128; jp++){
        u64 aj = *(const u64*)&a_s[2*jp];
        u64 bj = *(const u64*)&b_s[2*jp];
        u64 sj = *(const u64*)&s_s[2*jp];
        #pragma unroll
        for (int u = 0; u < 16; u++){
            u64 tt = fma2(vv[u], aj, bj);
            float p, q; upk2(tt, p, q);
            p = fmaxf(p, 0.f);
            q = fmaxf(q, 0.f);
            acc[u] = fma2(pk2(p, q), sj, acc[u]);
        }
    }

    float B2v = g_B2;
    #pragma unroll
    for (int u = 0; u < 16; u++){
        float p, q; upk2(acc[u], p, q);
        d_out[(u*256 + t)*Dd + i] = (p + q) + B2v;
    }
}

// ---------------- launch ---------------------------------------------------
extern "C" void kernel_launch(void* const* d_in, const int* in_sizes, int n_in,
                              void* d_out, int out_size)
{
    (void)in_sizes; (void)n_in; (void)out_size;
    const float* x      = (const float*)d_in[0];
    const float* weight = (const float*)d_in[1];
    const float* bias   = (const float*)d_in[2];
    const float* A      = (const float*)d_in[3];
    const float* W1     = (const float*)d_in[4];
    const float* b1     = (const float*)d_in[5];
    const float* W2     = (const float*)d_in[6];
    const float* b2     = (const float*)d_in[7];
    float* out = (float*)d_out;

    prep_kernel<<<1, 256>>>(weight, A, W2, b2, out);

    gemm_kernel<<<128, 256>>>(x, bias);
    f_kernel<<<128, 256>>>(W1, b1, out);

    // Exact jnp.linalg.matrix_power(M, 127) binary ladder (12 fp32 matmuls):
    // z: M^2, M^4, ... M^64 ; result: M^3, M^7, M^15, M^31, M^63, M^127
    mm_kernel<<<128, 128>>>(IDX_M,  IDX_M,  IDX_ZA);  // Z  = M^2
    mm_kernel<<<128, 128>>>(IDX_M,  IDX_ZA, IDX_RA);  // R  = M @ M^2   = M^3
    mm_kernel<<<128, 128>>>(IDX_ZA, IDX_ZA, IDX_ZB);  // Z  = M^4
    mm_kernel<<<128, 128>>>(IDX_RA, IDX_ZB, IDX_RB);  // R  = M^3 @ M^4 = M^7
    mm_kernel<<<128, 128>>>(IDX_ZB, IDX_ZB, IDX_ZA);  // Z  = M^8
    mm_kernel<<<128, 128>>>(IDX_RB, IDX_ZA, IDX_RA);  // R  = M^15
    mm_kernel<<<128, 128>>>(IDX_ZA, IDX_ZA, IDX_ZB);  // Z  = M^16
    mm_kernel<<<128, 128>>>(IDX_RA, IDX_ZB, IDX_RB);  // R  = M^31
    mm_kernel<<<128, 128>>>(IDX_ZB, IDX_ZB, IDX_ZA);  // Z  = M^32
    mm_kernel<<<128, 128>>>(IDX_RB, IDX_ZA, IDX_RA);  // R  = M^63
    mm_kernel<<<128, 128>>>(IDX_ZA, IDX_ZA, IDX_ZB);  // Z  = M^64
    mm_kernel<<<128, 128>>>(IDX_RA, IDX_ZB, IDX_RB);  // R  = M^127 = E

    hsum_kernel<<<1, 32>>>(IDX_RB, out);
}

// round 4
// speedup vs baseline: 1.3033x; 1.3033x over previous
#include <cuda_runtime.h>

#define Nn 4096
#define Dd 128
#define H1h 256

typedef unsigned long long u64;

// ---------------- device scratch ------------------------------------------
__device__ float g_Wt [Dd*Dd];    // transpose of W=weight*A (for gemm)
__device__ float g_M  [Dd*Dd];    // M = I + W^2/D (fp32, as reference rounds)
// ladder buffers: each power written exactly once
__device__ float g_P2[Dd*Dd],  g_P3[Dd*Dd],  g_P4[Dd*Dd],  g_P7[Dd*Dd];
__device__ float g_P8[Dd*Dd],  g_P15[Dd*Dd], g_P16[Dd*Dd], g_P31[Dd*Dd];
__device__ float g_P32[Dd*Dd], g_P63[Dd*Dd], g_P64[Dd*Dd], g_P127[Dd*Dd];
__device__ float g_s2[H1h];
__device__ float g_B2;
__device__ float g_y [Nn*Dd];     // y = x@W + bias  ([n][i])
// piecewise-linear tables per column i
__device__ float g_T [Dd*256];    // sorted breakpoints
__device__ float g_Pa[Dd*257];    // slope  prefix table
__device__ float g_Pb[Dd*257];    // offset prefix table (includes B2, C0)

// grid barrier state (sense-reversal; safe across graph replays)
__device__ volatile unsigned g_gen = 0;
__device__ unsigned g_cnt = 0;

// ---------------- packed f32x2 helpers ------------------------------------
__device__ __forceinline__ u64 pk2(float lo, float hi){
    u64 r; asm("mov.b64 %0, {%1, %2};" : "=l"(r) : "f"(lo), "f"(hi)); return r;
}
__device__ __forceinline__ void upk2(u64 v, float& lo, float& hi){
    asm("mov.b64 {%0, %1}, %2;" : "=f"(lo), "=f"(hi) : "l"(v));
}
__device__ __forceinline__ u64 fma2(u64 a, u64 b, u64 c){
    u64 d; asm("fma.rn.f32x2 %0, %1, %2, %3;" : "=l"(d) : "l"(a), "l"(b), "l"(c));
    return d;
}

// ---------------- prep: Wt, M, s2, B2, reg ---------------------------------
__global__ void prep_kernel(const float* __restrict__ weight,
                            const float* __restrict__ A,
                            const float* __restrict__ W2,
                            const float* __restrict__ b2,
                            float* __restrict__ d_out)
{
    __shared__ float red[256];
    int t = threadIdx.x; // 256
    float labs = 0.f;
    for (int idx = t; idx < Dd*Dd; idx += 256){
        float w = weight[idx] * A[idx];
        int r = idx >> 7, c = idx & 127;
        g_Wt[c*Dd + r] = w;
        g_M[idx] = (r == c ? 1.f : 0.f) + (w*w)*(1.f/128.f);
        labs += fabsf(w);
    }
    // s2[j]: warp-cooperative coalesced row sums of W2 [256,128]
    {
        int w = t >> 5, lane = t & 31;
        for (int rr = 0; rr < 32; rr++){
            int row = w*32 + rr;
            const float* p = W2 + row*128;
            float v = (p[lane] + p[lane+32]) + (p[lane+64] + p[lane+96]);
            #pragma unroll
            for (int s = 16; s > 0; s >>= 1)
                v += __shfl_xor_sync(0xffffffffu, v, s);
            if (lane == 0) g_s2[row] = v;
        }
    }
    // B2 = sum(b2), tree over 128 threads
    red[t] = (t < 128) ? b2[t] : 0.f;
    __syncthreads();
    for (int s = 128; s > 0; s >>= 1){
        if (t < s) red[t] += red[t + s];
        __syncthreads();
    }
    if (t == 0) g_B2 = red[0];
    __syncthreads();
    // reg = sum |W| (same structure as passing version)
    red[t] = labs;
    __syncthreads();
    for (int s = 128; s > 0; s >>= 1){
        if (t < s) red[t] += red[t + s];
        __syncthreads();
    }
    if (t == 0) d_out[Nn*Dd + 1] = red[0];
}

// ---------------- grid barrier ---------------------------------------------
__device__ __forceinline__ void gridbar(){
    __syncthreads();
    __threadfence();
    if (threadIdx.x == 0){
        unsigned g = g_gen;
        if (atomicAdd(&g_cnt, 1) == gridDim.x - 1){
            g_cnt = 0;
            __threadfence();
            g_gen = g + 1;
        } else {
            while (g_gen == g) { }
        }
    }
    __syncthreads();
}

// single-chain ascending-k dot (bit-identical to the passing mm_kernel),
// with a 32-deep register prefetch ring over L2 (__ldcg: bypass stale L1).
__device__ __forceinline__ float mm_row(const float* Ls, const float* Rm, int j){
    const float* Rp = Rm + j;
    float buf[32];
    #pragma unroll
    for (int k = 0; k < 32; k++) buf[k] = __ldcg(Rp + k*128);
    float acc = 0.f;
    #pragma unroll
    for (int k = 0; k < 96; k++){
        float cur = buf[k & 31];
        buf[k & 31] = __ldcg(Rp + (k+32)*128);
        acc = fmaf(Ls[k], cur, acc);
    }
    #pragma unroll
    for (int k = 96; k < 128; k++)
        acc = fmaf(Ls[k], buf[k & 31], acc);
    return acc;
}

// ---- fused ladder: 7 levels (<=2 products each) + hsum, one launch --------
__global__ void ladder_kernel(float* __restrict__ d_out)
{
    __shared__ float Ls[256];
    int t = threadIdx.x, r = blockIdx.x;
    int half = t >> 7, j = t & 127;

    #define LEVEL2(LA, RA, DA, LB, RB, DB)                                  \
    {                                                                       \
        if (half == 0) Ls[j]       = __ldcg(&LA[r*128 + j]);                \
        else           Ls[128 + j] = __ldcg(&LB[r*128 + j]);                \
        __syncthreads();                                                    \
        if (half == 0) DA[r*128 + j] = mm_row(Ls,       RA, j);             \
        else           DB[r*128 + j] = mm_row(Ls + 128, RB, j);             \
        gridbar();                                                          \
    }
    #define LEVEL1(LA, RA, DA)                                              \
    {                                                                       \
        if (half == 0) Ls[j] = __ldcg(&LA[r*128 + j]);                      \
        __syncthreads();                                                    \
        if (half == 0) DA[r*128 + j] = mm_row(Ls, RA, j);                   \
        gridbar();                                                          \
    }

    LEVEL1(g_M,   g_M,   g_P2 )
    LEVEL2(g_M,   g_P2,  g_P3 ,  g_P2,  g_P2,  g_P4 )
    LEVEL2(g_P3,  g_P4,  g_P7 ,  g_P4,  g_P4,  g_P8 )
    LEVEL2(g_P7,  g_P8,  g_P15,  g_P8,  g_P8,  g_P16)
    LEVEL2(g_P15, g_P16, g_P31,  g_P16, g_P16, g_P32)
    LEVEL2(g_P31, g_P32, g_P63,  g_P32, g_P32, g_P64)
    LEVEL1(g_P63, g_P64, g_P127)

    // hsum: identical arithmetic to the passing version
    if (blockIdx.x == 0 && t < 32){
        __shared__ float p[32];
        int l = t;
        float s = 0.f;
        for (int it = 0; it < 512; it++){
            int idx = l + (it << 5);
            int i = idx >> 7, jj = idx & 127;
            s += __ldcg(&g_P127[jj*128 + i]) * __ldcg(&g_M[i*128 + jj]);
        }
        p[l] = s;
        __syncwarp();
        for (int st = 16; st > 0; st >>= 1){
            if (l < st) p[l] += p[l + st];
            __syncwarp();
        }
        if (l == 0) d_out[Nn*Dd] = p[0] - 128.f;
    }
}

// ---------------- y = x @ W + bias (unchanged, passing) --------------------
__global__ void gemm_kernel(const float* __restrict__ x,
                            const float* __restrict__ bias)
{
    __shared__ __align__(16) float xs[32][128];
    int t  = threadIdx.x;            // 256
    int n0 = blockIdx.x * 32;        // 128 blocks
    for (int idx = t; idx < 32*128; idx += 256)
        xs[idx >> 7][idx & 127] = x[n0*128 + idx];
    __syncthreads();

    int i  = t & 127;
    int ng = t >> 7;
    const u64* wrow = (const u64*)(g_Wt + i*128);
    u64 acc[16];
    #pragma unroll
    for (int u = 0; u < 16; u++) acc[u] = 0ULL;

    for (int d2 = 0; d2 < 64; d2 += 2){
        u64 w01 = wrow[d2];
        u64 w23 = wrow[d2 + 1];
        #pragma unroll
        for (int u = 0; u < 16; u++){
            const u64* xp = (const u64*)&xs[ng*16 + u][d2*2];
            acc[u] = fma2(xp[0], w01, acc[u]);
            acc[u] = fma2(xp[1], w23, acc[u]);
        }
    }
    float bi = bias[i];
    #pragma unroll
    for (int u = 0; u < 16; u++){
        float p, q; upk2(acc[u], p, q);
        g_y[(n0 + ng*16 + u)*Dd + i] = (p + q) + bi;
    }
}

// ---- fsetup: per column i, sort breakpoints + prefix tables ---------------
// f[n,i] = sum_j relu(y*a_j + b_j)*s_j + B2 is piecewise-linear in y:
//   f(y) = y*Pa[k] + Pb[k],  k = #{j : t_j < y},  t_j = -b_j/a_j
__global__ void fsetup_kernel(const float* __restrict__ W1,
                              const float* __restrict__ b1)
{
    __shared__ float key[256]; __shared__ int sidx[256];
    __shared__ float asA[256], bsA[256];
    __shared__ int   upA[256];
    __shared__ float UA[256], UB[256], DA[256], DB[256];
    __shared__ float red[256];

    int i = blockIdx.x, t = threadIdx.x;
    float a = W1[i*H1h + t];
    float b = b1[t];
    float s = g_s2[t];
    float as = a*s, bs = b*s;
    float tb; int up; float c0 = 0.f;
    if (a > 0.f)      { tb = -b/a; up = 1; }
    else if (a < 0.f) { tb = -b/a; up = 0; }
    else { tb = __int_as_float(0x7f800000); up = 1; as = 0.f; bs = 0.f;
           c0 = fmaxf(b, 0.f) * s; }

    key[t] = tb; sidx[t] = t;
    asA[t] = as; bsA[t] = bs; upA[t] = up;
    __syncthreads();

    // bitonic sort of (key, sidx), ascending
    for (int ksz = 2; ksz <= 256; ksz <<= 1){
        for (int jsz = ksz >> 1; jsz > 0; jsz >>= 1){
            int ixj = t ^ jsz;
            float k0 = key[t], k1 = key[ixj];
            int   i0 = sidx[t], i1 = sidx[ixj];
            __syncthreads();
            if (ixj > t){
                bool asc = ((t & ksz) == 0);
                bool sw  = asc ? (k0 > k1) : (k0 < k1);
                if (sw){ key[t] = k1; key[ixj] = k0;
                         sidx[t] = i1; sidx[ixj] = i0; }
            }
            __syncthreads();
        }
    }

    // gather payloads in sorted order, split by direction
    int o = sidx[t];
    float pas = asA[o], pbs = bsA[o];
    int pup = upA[o];
    UA[t] = pup ? pas : 0.f;  UB[t] = pup ? pbs : 0.f;
    DA[t] = pup ? 0.f : pas;  DB[t] = pup ? 0.f : pbs;
    __syncthreads();

    // inclusive Hillis-Steele scans
    for (int off = 1; off < 256; off <<= 1){
        float ua = (t >= off) ? UA[t-off] : 0.f;
        float ub = (t >= off) ? UB[t-off] : 0.f;
        float da = (t >= off) ? DA[t-off] : 0.f;
        float db = (t >= off) ? DB[t-off] : 0.f;
        __syncthreads();
        UA[t] += ua; UB[t] += ub; DA[t] += da; DB[t] += db;
        __syncthreads();
    }

    // C0 (a==0 constants) + B2
    red[t] = c0;
    __syncthreads();
    for (int st = 128; st > 0; st >>= 1){
        if (t < st) red[t] += red[t + st];
        __syncthreads();
    }
    float C0 = red[0] + g_B2;
    float totDA = DA[255], totDB = DB[255];

    float exUA = (t > 0) ? UA[t-1] : 0.f;
    float exUB = (t > 0) ? UB[t-1] : 0.f;
    float exDA = (t > 0) ? DA[t-1] : 0.f;
    float exDB = (t > 0) ? DB[t-1] : 0.f;

    g_T [i*256 + t] = key[t];
    g_Pa[i*257 + t] = exUA + (totDA - exDA);
    g_Pb[i*257 + t] = exUB + (totDB - exDB) + C0;
    if (t == 255){
        g_Pa[i*257 + 256] = UA[255];
        g_Pb[i*257 + 256] = UB[255] + C0;
    }
}

// ---- feval: block = 32 i-cols x 128 n-rows; smem tables; bsearch + 1 FMA --
__global__ void feval_kernel(float* __restrict__ d_out)
{
    extern __shared__ float dyn[];
    float* sT  = dyn;              // [32][257] (pos 256 padding)
    float* sPa = sT  + 32*257;     // [32][257]
    float* sPb = sPa + 32*257;     // [32][257]

    int t  = threadIdx.x;          // 256
    int bi = blockIdx.x & 3,  bn = blockIdx.x >> 2;
    int i0 = bi*32, n0 = bn*128;

    for (int idx = t; idx < 32*257; idx += 256){
        int ii = idx / 257, kk = idx - ii*257;
        sT [idx] = (kk < 256) ? g_T[(i0+ii)*256 + kk] : __int_as_float(0x7f800000);
        sPa[idx] = g_Pa[(i0+ii)*257 + kk];
        sPb[idx] = g_Pb[(i0+ii)*257 + kk];
    }
    __syncthreads();

    int lane = t & 31, w = t >> 5;
    const float* Tl = sT + lane*257;
    const float* Pal = sPa + lane*257;
    const float* Pbl = sPb + lane*257;

    #pragma unroll 4
    for (int pass = 0; pass < 16; pass++){
        int n = n0 + w + pass*8;
        float y = g_y[n*Dd + i0 + lane];
        int k = 0;
        #pragma unroll
        for (int stp = 128; stp > 0; stp >>= 1)
            if (Tl[k + stp - 1] < y) k += stp;
        d_out[n*Dd + i0 + lane] = fmaf(y, Pal[k], Pbl[k]);
    }
}

// ---------------- launch ----------------------------------------------------
extern "C" void kernel_launch(void* const* d_in, const int* in_sizes, int n_in,
                              void* d_out, int out_size)
{
    (void)in_sizes; (void)n_in; (void)out_size;
    const float* x      = (const float*)d_in[0];
    const float* weight = (const float*)d_in[1];
    const float* bias   = (const float*)d_in[2];
    const float* A      = (const float*)d_in[3];
    const float* W1     = (const float*)d_in[4];
    const float* b1     = (const float*)d_in[5];
    const float* W2     = (const float*)d_in[6];
    const float* b2     = (const float*)d_in[7];
    float* out = (float*)d_out;

    static bool attr_done = false;
    if (!attr_done){
        cudaFuncSetAttribute(feval_kernel,
                             cudaFuncAttributeMaxDynamicSharedMemorySize,
                             3*32*257*(int)sizeof(float));
        attr_done = true;
    }

    prep_kernel  <<<1,   256>>>(weight, A, W2, b2, out);
    fsetup_kernel<<<128, 256>>>(W1, b1);
    gemm_kernel  <<<128, 256>>>(x, bias);
    feval_kernel <<<128, 256, 3*32*257*(int)sizeof(float)>>>(out);
    ladder_kernel<<<128, 256>>>(out);
}